// round 7
// baseline (speedup 1.0000x reference)
#include <cuda_runtime.h>
#include <stdint.h>
#include <math.h>

// Problem constants
#define NBATCH 4
#define PREK   1024
#define NBUCK  65536      // 16-bit buckets of float bits (scores are positive)
#define CAP    2048       // candidate capacity per batch
#define MAXN   262144     // >= 200000
#define NEGBIG (-1e9f)

// ---------------- device scratch (no allocations allowed) ----------------
__device__ float              g_boxes[MAXN * 8];          // decoded boxes (7 used)
__device__ unsigned           g_sbits[MAXN];              // score as ordered uint
__device__ int                g_hist[NBATCH * NBUCK];     // per-batch histogram
__device__ float              g_vals[NBATCH * PREK];      // top-k scores
__device__ float              g_box7[NBATCH * PREK * 7];  // gathered boxes
__device__ float              g_x1[NBATCH * PREK], g_x2[NBATCH * PREK];
__device__ float              g_y1[NBATCH * PREK], g_y2[NBATCH * PREK];
__device__ float              g_ar[NBATCH * PREK];
__device__ unsigned           g_rows[NBATCH * PREK * 32]; // suppression bitmask rows
__device__ unsigned           g_rowAny[NBATCH * 32];      // rows with any overlap

// ---------------- K0: zero histogram + rowAny (single small launch) -------
__global__ void k_zero() {
    int i = blockIdx.x * blockDim.x + threadIdx.x;
    if (i < NBATCH * NBUCK) g_hist[i] = 0;
    if (i < NBATCH * 32)    g_rowAny[i] = 0;
}

// ---------------- K1: GEMV + decode + histogram, 2 points/warp ------------
// GEMV math bitwise-identical to the R6-passing kernel:
//   per-lane partial = 8 sequential FMAs over features [8L,8L+8) (R1 order),
//   level-16 via exchange SHFL, levels 8,4,2,1 via xor butterfly in halves.
// After the butterfly every lane of a half holds ALL 11 sums, so lane 0
// (point A) and lane 16 (point B) run the decode epilogue concurrently.
// Decode float-op sequence identical to the R6-passing k_decode.
__global__ __launch_bounds__(256) void k_gemv(
    const float* __restrict__ feat,
    const float* __restrict__ Wc, const float* __restrict__ Wr,
    const float* __restrict__ bc, const float* __restrict__ br,
    const int* __restrict__ bidx, const int* __restrict__ coor, int n)
{
    int lane  = threadIdx.x & 31;
    int warp  = (blockIdx.x * blockDim.x + threadIdx.x) >> 5;
    int nwarp = (gridDim.x * blockDim.x) >> 5;
    int c0 = lane * 8;

    // weight slice in registers, R1 layout
    float w[11][8];
#pragma unroll
    for (int i = 0; i < 8; i++) {
        w[0][i] = Wc[(c0 + i) * 2 + 0];
        w[1][i] = Wc[(c0 + i) * 2 + 1];
#pragma unroll
        for (int o = 0; o < 9; o++) w[2 + o][i] = Wr[(c0 + i) * 9 + o];
    }
    float bc0 = bc[0], bc1 = bc[1];
    float brr[9];
#pragma unroll
    for (int o = 0; o < 9; o++) brr[o] = br[o];

    bool hi = (lane & 16) != 0;
    int  oo = lane & 15;
    int npair = (n + 1) >> 1;

    int pr = warp;
    if (pr >= npair) return;

    int pA = 2 * pr, pBs = (pA + 1 < n) ? pA + 1 : pA;
    float4 A0 = *reinterpret_cast<const float4*>(feat + (size_t)pA  * 256 + c0);
    float4 A1 = *reinterpret_cast<const float4*>(feat + (size_t)pA  * 256 + c0 + 4);
    float4 B0 = *reinterpret_cast<const float4*>(feat + (size_t)pBs * 256 + c0);
    float4 B1 = *reinterpret_cast<const float4*>(feat + (size_t)pBs * 256 + c0 + 4);

    while (pr < npair) {
        int prn = pr + nwarp;
        float4 An0, An1, Bn0, Bn1;
        if (prn < npair) {               // prefetch next pair
            int qA = 2 * prn, qB = (qA + 1 < n) ? qA + 1 : qA;
            An0 = *reinterpret_cast<const float4*>(feat + (size_t)qA * 256 + c0);
            An1 = *reinterpret_cast<const float4*>(feat + (size_t)qA * 256 + c0 + 4);
            Bn0 = *reinterpret_cast<const float4*>(feat + (size_t)qB * 256 + c0);
            Bn1 = *reinterpret_cast<const float4*>(feat + (size_t)qB * 256 + c0 + 4);
        }

        float fvA[8] = {A0.x, A0.y, A0.z, A0.w, A1.x, A1.y, A1.z, A1.w};
        float fvB[8] = {B0.x, B0.y, B0.z, B0.w, B1.x, B1.y, B1.z, B1.w};

        float aA[11], aB[11];
#pragma unroll
        for (int o = 0; o < 11; o++) { aA[o] = 0.f; aB[o] = 0.f; }
#pragma unroll
        for (int i = 0; i < 8; i++)
#pragma unroll
            for (int o = 0; o < 11; o++) {
                aA[o] += fvA[i] * w[o][i];
                aB[o] += fvB[i] * w[o][i];
            }

        float cur[11];
#pragma unroll
        for (int o = 0; o < 11; o++) {
            float v = hi ? aA[o] : aB[o];
            float r = __shfl_xor_sync(0xffffffffu, v, 16);
            float mine = hi ? aB[o] : aA[o];
            cur[o] = mine + r;
        }
#pragma unroll
        for (int off = 8; off >= 1; off >>= 1)
#pragma unroll
            for (int o = 0; o < 11; o++)
                cur[o] += __shfl_xor_sync(0xffffffffu, cur[o], off);

        // decode epilogue: lane 0 handles point A, lane 16 handles point B
        int p = 2 * pr + (hi ? 1 : 0);
        if (oo == 0 && p < n) {
            float l0 = cur[0] + bc0, l1 = cur[1] + bc1;
            float conf = 1.f / (1.f + expf(l0 - l1));
            float r0 = cur[2] + brr[0], r1 = cur[3] + brr[1], r2 = cur[4] + brr[2];
            float r3 = cur[5] + brr[3], r4v = cur[6] + brr[4], r5 = cur[7] + brr[5];
            float r6 = cur[8] + brr[6], r7 = cur[9] + brr[7], r8 = cur[10] + brr[8];
            float scr = 1.f / (1.f + expf(-r8));
            float score = conf * scr;

            float cx = (float)coor[2 * p]     * 0.8f + r0;
            float cy = (float)coor[2 * p + 1] * 0.8f + r1;
            float L  = expf(fminf(fmaxf(r3,  -6.f), 6.f));
            float Wd = expf(fminf(fmaxf(r4v, -6.f), 6.f));
            float H  = expf(fminf(fmaxf(r5,  -6.f), 6.f));
            float ang = atan2f(r6, r7);

            float4* b4 = reinterpret_cast<float4*>(g_boxes + (size_t)p * 8);
            b4[0] = make_float4(cx, cy, r2, L);
            b4[1] = make_float4(Wd, H, ang, 0.f);

            unsigned sb = __float_as_uint(score);
            g_sbits[p] = sb;
            atomicAdd(&g_hist[bidx[p] * NBUCK + (sb >> 16)], 1);
        }

        pr = prn;
        A0 = An0; A1 = An1; B0 = Bn0; B1 = Bn1;
    }
}

// ---------------- K2: fused tail (cutoff + compact + sort + gather) -------
// One block per batch, 1024 threads.
__global__ __launch_bounds__(1024) void k_tail(
    const int* __restrict__ bidx, int n)
{
    __shared__ unsigned long long sk[CAP];       // 16 KB sort keys
    __shared__ int cs[256];
    __shared__ int Sarr[257];
    __shared__ int scnt;
    __shared__ int scut;

    int b = blockIdx.x, t = threadIdx.x;

    if (t == 0) scnt = 0;
    for (int i = t; i < CAP; i += 1024) sk[i] = 0ULL;

    // ---- cutoff on warps 0..7 (named barrier, 256 threads) ----
    if (t < 256) {
        const int4* h4 = reinterpret_cast<const int4*>(g_hist + b * NBUCK + t * 256);
        int s = 0;
#pragma unroll 8
        for (int i = 0; i < 64; i++) { int4 v = h4[i]; s += v.x + v.y + v.z + v.w; }
        cs[t] = s;
        asm volatile("bar.sync 1, 256;" ::: "memory");
        int S = 0;
        for (int u = t; u < 256; u++) S += cs[u];
        Sarr[t] = S;
        if (t == 0) Sarr[256] = 0;
        asm volatile("bar.sync 1, 256;" ::: "memory");
        if (S >= PREK && Sarr[t + 1] < PREK) {
            int running = Sarr[t + 1];
            int cut = t * 256;
            for (int bk = t * 256 + 255; bk >= t * 256; --bk) {
                running += g_hist[b * NBUCK + bk];
                if (running >= PREK) { cut = bk; break; }
            }
            scut = cut;
        }
        if (t == 0 && Sarr[0] < PREK) scut = 0;
    }
    __syncthreads();

    // ---- compact (all 1024 threads scan all points, filter batch b) ----
    int cut = scut;
    int nq = (n + 3) >> 2;
    for (int q = t; q < nq; q += 1024) {
        int i0 = q * 4;
        if (i0 + 3 < n) {
            int4 bv = *reinterpret_cast<const int4*>(bidx + i0);
            uint4 sv = *reinterpret_cast<const uint4*>(g_sbits + i0);
            int bb[4] = {bv.x, bv.y, bv.z, bv.w};
            unsigned ss[4] = {sv.x, sv.y, sv.z, sv.w};
#pragma unroll
            for (int k = 0; k < 4; k++) {
                if (bb[k] == b && (int)(ss[k] >> 16) >= cut) {
                    int pos = atomicAdd(&scnt, 1);
                    if (pos < CAP)
                        sk[pos] = ((unsigned long long)ss[k] << 32) |
                                  (unsigned long long)(0xFFFFFFFFu - (unsigned)(i0 + k));
                }
            }
        } else {
            for (int i = i0; i < n; i++) {
                if (bidx[i] == b && (int)(g_sbits[i] >> 16) >= cut) {
                    int pos = atomicAdd(&scnt, 1);
                    if (pos < CAP)
                        sk[pos] = ((unsigned long long)g_sbits[i] << 32) |
                                  (unsigned long long)(0xFFFFFFFFu - (unsigned)i);
                }
            }
        }
    }
    __syncthreads();

    // ---- bitonic sort (descending) ----
    for (int k = 2; k <= CAP; k <<= 1) {
        for (int j = k >> 1; j > 0; j >>= 1) {
#pragma unroll
            for (int r = 0; r < CAP / 1024; r++) {
                int i = t + r * 1024;
                int l = i ^ j;
                if (l > i) {
                    unsigned long long A = sk[i], B = sk[l];
                    bool desc = ((i & k) == 0);
                    if (desc ? (A < B) : (A > B)) { sk[i] = B; sk[l] = A; }
                }
            }
            __syncthreads();
        }
    }

    // ---- gather top-1024 ----
    if (t < PREK) {
        unsigned long long key = sk[t];
        unsigned idx = 0xFFFFFFFFu - (unsigned)(key & 0xFFFFFFFFull);
        float val = __uint_as_float((unsigned)(key >> 32));
        bool ok = (key != 0ULL) && (idx < (unsigned)n);
        float bx[7];
        if (ok) {
            const float4* p4 = reinterpret_cast<const float4*>(g_boxes + (size_t)idx * 8);
            float4 A = p4[0], B = p4[1];
            bx[0] = A.x; bx[1] = A.y; bx[2] = A.z; bx[3] = A.w;
            bx[4] = B.x; bx[5] = B.y; bx[6] = B.z;
        } else {
#pragma unroll
            for (int c = 0; c < 7; c++) bx[c] = 0.f;
            val = NEGBIG;
        }
        int o = b * PREK + t;
        g_vals[o] = val;
#pragma unroll
        for (int c = 0; c < 7; c++) g_box7[o * 7 + c] = bx[c];
        float hx = bx[3] * 0.5f, hy = bx[4] * 0.5f;
        g_x1[o] = bx[0] - hx; g_x2[o] = bx[0] + hx;
        g_y1[o] = bx[1] - hy; g_y2[o] = bx[1] + hy;
        g_ar[o] = bx[3] * bx[4];
    }
}

// ---------------- K3: suppression bitmask rows (fully parallel) -----------
__global__ void k_iou() {
    int tid = blockIdx.x * blockDim.x + threadIdx.x;
    if (tid >= NBATCH * PREK * 8) return;
    int b   = tid >> 13;
    int rem = tid & 8191;
    int i   = rem >> 3;
    int c   = rem & 7;
    int o = b * PREK;
    float x1 = g_x1[o + i], x2 = g_x2[o + i];
    float y1 = g_y1[o + i], y2 = g_y2[o + i], ar = g_ar[o + i];
    unsigned w0 = 0, w1 = 0, w2 = 0, w3 = 0;
    int j0 = c * 128;
#pragma unroll 4
    for (int jj = 0; jj < 128; jj++) {
        int j = j0 + jj;
        if (j <= i) continue;
        float ix = fmaxf(fminf(x2, g_x2[o + j]) - fmaxf(x1, g_x1[o + j]), 0.f);
        float iy = fmaxf(fminf(y2, g_y2[o + j]) - fmaxf(y1, g_y1[o + j]), 0.f);
        float inter = ix * iy;
        float uni = ar + g_ar[o + j] - inter;
        float iou = inter / fmaxf(uni, 1e-6f);
        if (iou > 0.1f) {
            unsigned bit = 1u << (jj & 31);
            if      (jj < 32) w0 |= bit;
            else if (jj < 64) w1 |= bit;
            else if (jj < 96) w2 |= bit;
            else              w3 |= bit;
        }
    }
    unsigned* rp = g_rows + ((size_t)(o + i)) * 32 + c * 4;
    rp[0] = w0; rp[1] = w1; rp[2] = w2; rp[3] = w3;
    if (w0 | w1 | w2 | w3)
        atomicOr(&g_rowAny[b * 32 + (i >> 5)], 1u << (i & 31));
}

// ---------------- K4: sparse sequential NMS scan + output -----------------
__global__ __launch_bounds__(1024) void k_nms_out(float* __restrict__ out, int out_size) {
    __shared__ unsigned supp[32];
    int b = blockIdx.x, t = threadIdx.x;
    if (t < 32) {
        unsigned sup = 0;
        unsigned myAny = g_rowAny[b * 32 + t];
        for (int w = 0; w < 32; w++) {
            unsigned aw = __shfl_sync(0xffffffffu, myAny, w);
            while (aw) {
                int bit = __ffs(aw) - 1;
                aw &= aw - 1;
                int i = w * 32 + bit;
                unsigned sw = __shfl_sync(0xffffffffu, sup, i >> 5);
                if (!((sw >> (i & 31)) & 1u))
                    sup |= g_rows[((size_t)(b * PREK + i)) * 32 + t];
            }
        }
        supp[t] = sup;
    }
    __syncthreads();
    int o = b * PREK + t;
    float val = g_vals[o];
    bool valid = val > -5e8f;
    bool kp = valid && !((supp[t >> 5] >> (t & 31)) & 1u);
    float m = kp ? 1.f : 0.f;
    size_t base = (size_t)o * 8;
#pragma unroll
    for (int c = 0; c < 7; c++)
        if ((int)(base + c) < out_size) out[base + c] = g_box7[o * 7 + c] * m;
    if ((int)(base + 7) < out_size) out[base + 7] = val * m;
    size_t lbOff = (size_t)NBATCH * PREK * 8 + o;
    if ((int)lbOff < out_size) out[lbOff] = 0.f;
    size_t kpOff = (size_t)NBATCH * PREK * 9 + o;
    if ((int)kpOff < out_size) out[kpOff] = m;
}

// ---------------- launch ----------------
extern "C" void kernel_launch(void* const* d_in, const int* in_sizes, int n_in,
                              void* d_out, int out_size) {
    const float* feat = (const float*)d_in[0];
    const int*   bidx = (const int*)  d_in[1];
    const int*   coor = (const int*)  d_in[2];
    const float* Wc   = (const float*)d_in[3];
    const float* bc   = (const float*)d_in[4];
    const float* Wr   = (const float*)d_in[5];
    const float* br   = (const float*)d_in[6];
    int n = in_sizes[1];

    k_zero   <<<NBATCH * NBUCK / 256, 256>>>();
    k_gemv   <<<1480, 256>>>(feat, Wc, Wr, bc, br, bidx, coor, n);
    k_tail   <<<NBATCH, 1024>>>(bidx, n);
    k_iou    <<<(NBATCH * PREK * 8 + 255) / 256, 256>>>();
    k_nms_out<<<NBATCH, 1024>>>((float*)d_out, out_size);
}

// round 8
// speedup vs baseline: 1.0085x; 1.0085x over previous
#include <cuda_runtime.h>
#include <stdint.h>
#include <math.h>

// Problem constants
#define NBATCH 4
#define PREK   1024
#define NBUCK  65536      // 16-bit buckets of float bits (scores are positive)
#define CAP    2048       // candidate capacity per batch
#define MAXN   262144     // >= 200000
#define NEGBIG (-1e9f)

// ---------------- device scratch (no allocations allowed) ----------------
__device__ float              g_boxes[MAXN * 8];          // decoded boxes (7 used)
__device__ unsigned           g_sbits[MAXN];              // score as ordered uint
__device__ int                g_hist[NBATCH * NBUCK];     // per-batch histogram
__device__ int                g_cut[NBATCH];              // cutoff bucket
__device__ int                g_cnt[NBATCH];              // candidate counters
__device__ unsigned long long g_cand[NBATCH * CAP];       // (score_bits<<32)|(~idx)
__device__ float              g_vals[NBATCH * PREK];      // top-k scores
__device__ float              g_box7[NBATCH * PREK * 7];  // gathered boxes
__device__ float              g_x1[NBATCH * PREK], g_x2[NBATCH * PREK];
__device__ float              g_y1[NBATCH * PREK], g_y2[NBATCH * PREK];
__device__ float              g_ar[NBATCH * PREK];
__device__ unsigned           g_rows[NBATCH * PREK * 32]; // suppression bitmask rows
__device__ unsigned           g_rowAny[NBATCH * 32];      // rows with any overlap

// ---------------- K0: zero scratch ----------------------------------------
__global__ void k_zero() {
    int i = blockIdx.x * blockDim.x + threadIdx.x;
    if (i < NBATCH * NBUCK) g_hist[i] = 0;
    if (i < NBATCH)         g_cnt[i]  = 0;
    if (i < NBATCH * 32)    g_rowAny[i] = 0;
}

// ---------------- K1: GEMV + decode + histogram, 2 points/warp ------------
// GEMV math bitwise-identical to the R6/R7-passing kernels.
__global__ __launch_bounds__(256) void k_gemv(
    const float* __restrict__ feat,
    const float* __restrict__ Wc, const float* __restrict__ Wr,
    const float* __restrict__ bc, const float* __restrict__ br,
    const int* __restrict__ bidx, const int* __restrict__ coor, int n)
{
    int lane  = threadIdx.x & 31;
    int warp  = (blockIdx.x * blockDim.x + threadIdx.x) >> 5;
    int nwarp = (gridDim.x * blockDim.x) >> 5;
    int c0 = lane * 8;

    float w[11][8];
#pragma unroll
    for (int i = 0; i < 8; i++) {
        w[0][i] = Wc[(c0 + i) * 2 + 0];
        w[1][i] = Wc[(c0 + i) * 2 + 1];
#pragma unroll
        for (int o = 0; o < 9; o++) w[2 + o][i] = Wr[(c0 + i) * 9 + o];
    }
    float bc0 = bc[0], bc1 = bc[1];
    float brr[9];
#pragma unroll
    for (int o = 0; o < 9; o++) brr[o] = br[o];

    bool hi = (lane & 16) != 0;
    int  oo = lane & 15;
    int npair = (n + 1) >> 1;

    int pr = warp;
    if (pr >= npair) return;

    int pA = 2 * pr, pBs = (pA + 1 < n) ? pA + 1 : pA;
    float4 A0 = *reinterpret_cast<const float4*>(feat + (size_t)pA  * 256 + c0);
    float4 A1 = *reinterpret_cast<const float4*>(feat + (size_t)pA  * 256 + c0 + 4);
    float4 B0 = *reinterpret_cast<const float4*>(feat + (size_t)pBs * 256 + c0);
    float4 B1 = *reinterpret_cast<const float4*>(feat + (size_t)pBs * 256 + c0 + 4);

    while (pr < npair) {
        int prn = pr + nwarp;
        float4 An0, An1, Bn0, Bn1;
        if (prn < npair) {
            int qA = 2 * prn, qB = (qA + 1 < n) ? qA + 1 : qA;
            An0 = *reinterpret_cast<const float4*>(feat + (size_t)qA * 256 + c0);
            An1 = *reinterpret_cast<const float4*>(feat + (size_t)qA * 256 + c0 + 4);
            Bn0 = *reinterpret_cast<const float4*>(feat + (size_t)qB * 256 + c0);
            Bn1 = *reinterpret_cast<const float4*>(feat + (size_t)qB * 256 + c0 + 4);
        }

        float fvA[8] = {A0.x, A0.y, A0.z, A0.w, A1.x, A1.y, A1.z, A1.w};
        float fvB[8] = {B0.x, B0.y, B0.z, B0.w, B1.x, B1.y, B1.z, B1.w};

        float aA[11], aB[11];
#pragma unroll
        for (int o = 0; o < 11; o++) { aA[o] = 0.f; aB[o] = 0.f; }
#pragma unroll
        for (int i = 0; i < 8; i++)
#pragma unroll
            for (int o = 0; o < 11; o++) {
                aA[o] += fvA[i] * w[o][i];
                aB[o] += fvB[i] * w[o][i];
            }

        float cur[11];
#pragma unroll
        for (int o = 0; o < 11; o++) {
            float v = hi ? aA[o] : aB[o];
            float r = __shfl_xor_sync(0xffffffffu, v, 16);
            float mine = hi ? aB[o] : aA[o];
            cur[o] = mine + r;
        }
#pragma unroll
        for (int off = 8; off >= 1; off >>= 1)
#pragma unroll
            for (int o = 0; o < 11; o++)
                cur[o] += __shfl_xor_sync(0xffffffffu, cur[o], off);

        int p = 2 * pr + (hi ? 1 : 0);
        if (oo == 0 && p < n) {
            float l0 = cur[0] + bc0, l1 = cur[1] + bc1;
            float conf = 1.f / (1.f + expf(l0 - l1));
            float r0 = cur[2] + brr[0], r1 = cur[3] + brr[1], r2 = cur[4] + brr[2];
            float r3 = cur[5] + brr[3], r4v = cur[6] + brr[4], r5 = cur[7] + brr[5];
            float r6 = cur[8] + brr[6], r7 = cur[9] + brr[7], r8 = cur[10] + brr[8];
            float scr = 1.f / (1.f + expf(-r8));
            float score = conf * scr;

            float cx = (float)coor[2 * p]     * 0.8f + r0;
            float cy = (float)coor[2 * p + 1] * 0.8f + r1;
            float L  = expf(fminf(fmaxf(r3,  -6.f), 6.f));
            float Wd = expf(fminf(fmaxf(r4v, -6.f), 6.f));
            float H  = expf(fminf(fmaxf(r5,  -6.f), 6.f));
            float ang = atan2f(r6, r7);

            float4* b4 = reinterpret_cast<float4*>(g_boxes + (size_t)p * 8);
            b4[0] = make_float4(cx, cy, r2, L);
            b4[1] = make_float4(Wd, H, ang, 0.f);

            unsigned sb = __float_as_uint(score);
            g_sbits[p] = sb;
            atomicAdd(&g_hist[bidx[p] * NBUCK + (sb >> 16)], 1);
        }

        pr = prn;
        A0 = An0; A1 = An1; B0 = Bn0; B1 = Bn1;
    }
}

// ---------------- K2: per-batch cutoff bucket from histogram --------------
__global__ __launch_bounds__(256) void k_cutoff() {
    int b = blockIdx.x, t = threadIdx.x;
    const int4* h4 = reinterpret_cast<const int4*>(g_hist + b * NBUCK + t * 256);
    int s = 0;
#pragma unroll 8
    for (int i = 0; i < 64; i++) { int4 v = h4[i]; s += v.x + v.y + v.z + v.w; }
    __shared__ int cs[256];
    __shared__ int Sarr[257];
    cs[t] = s;
    __syncthreads();
    int S = 0;
    for (int u = t; u < 256; u++) S += cs[u];
    Sarr[t] = S;
    if (t == 0) Sarr[256] = 0;
    __syncthreads();
    if (S >= PREK && Sarr[t + 1] < PREK) {
        int running = Sarr[t + 1];
        int cut = t * 256;
        for (int bk = t * 256 + 255; bk >= t * 256; --bk) {
            running += g_hist[b * NBUCK + bk];
            if (running >= PREK) { cut = bk; break; }
        }
        g_cut[b] = cut;
    }
    if (t == 0 && Sarr[0] < PREK) g_cut[b] = 0;
}

// ---------------- K3: compact candidates >= cutoff bucket (x4 vec) --------
__global__ void k_compact(const int* __restrict__ bidx, int n) {
    int q = blockIdx.x * blockDim.x + threadIdx.x;
    int i0 = q * 4;
    if (i0 >= n) return;
    if (i0 + 3 < n) {
        int4 bv = *reinterpret_cast<const int4*>(bidx + i0);
        uint4 sv = *reinterpret_cast<const uint4*>(g_sbits + i0);
        int bb[4] = {bv.x, bv.y, bv.z, bv.w};
        unsigned ss[4] = {sv.x, sv.y, sv.z, sv.w};
#pragma unroll
        for (int k = 0; k < 4; k++) {
            if ((int)(ss[k] >> 16) >= g_cut[bb[k]]) {
                int pos = atomicAdd(&g_cnt[bb[k]], 1);
                if (pos < CAP)
                    g_cand[bb[k] * CAP + pos] =
                        ((unsigned long long)ss[k] << 32) |
                        (unsigned long long)(0xFFFFFFFFu - (unsigned)(i0 + k));
            }
        }
    } else {
        for (int i = i0; i < n; i++) {
            int b = bidx[i];
            unsigned sb = g_sbits[i];
            if ((int)(sb >> 16) >= g_cut[b]) {
                int pos = atomicAdd(&g_cnt[b], 1);
                if (pos < CAP)
                    g_cand[b * CAP + pos] =
                        ((unsigned long long)sb << 32) |
                        (unsigned long long)(0xFFFFFFFFu - (unsigned)i);
            }
        }
    }
}

// ---------------- K4: per-batch bitonic sort + gather top-1024 ------------
__global__ __launch_bounds__(1024) void k_sort(int n) {
    __shared__ unsigned long long sk[CAP];
    int b = blockIdx.x, t = threadIdx.x;
    int cnt = g_cnt[b]; if (cnt > CAP) cnt = CAP;
#pragma unroll
    for (int r = 0; r < CAP / 1024; r++) {
        int i = t + r * 1024;
        sk[i] = (i < cnt) ? g_cand[b * CAP + i] : 0ULL;
    }
    __syncthreads();
    for (int k = 2; k <= CAP; k <<= 1) {
        for (int j = k >> 1; j > 0; j >>= 1) {
#pragma unroll
            for (int r = 0; r < CAP / 1024; r++) {
                int i = t + r * 1024;
                int l = i ^ j;
                if (l > i) {
                    unsigned long long A = sk[i], B = sk[l];
                    bool desc = ((i & k) == 0);
                    if (desc ? (A < B) : (A > B)) { sk[i] = B; sk[l] = A; }
                }
            }
            __syncthreads();
        }
    }
    if (t < PREK) {
        unsigned long long key = sk[t];
        unsigned idx = 0xFFFFFFFFu - (unsigned)(key & 0xFFFFFFFFull);
        float val = __uint_as_float((unsigned)(key >> 32));
        bool ok = (key != 0ULL) && (idx < (unsigned)n);
        float bx[7];
        if (ok) {
            const float4* p4 = reinterpret_cast<const float4*>(g_boxes + (size_t)idx * 8);
            float4 A = p4[0], B = p4[1];
            bx[0] = A.x; bx[1] = A.y; bx[2] = A.z; bx[3] = A.w;
            bx[4] = B.x; bx[5] = B.y; bx[6] = B.z;
        } else {
#pragma unroll
            for (int c = 0; c < 7; c++) bx[c] = 0.f;
            val = NEGBIG;
        }
        int o = b * PREK + t;
        g_vals[o] = val;
#pragma unroll
        for (int c = 0; c < 7; c++) g_box7[o * 7 + c] = bx[c];
        float hx = bx[3] * 0.5f, hy = bx[4] * 0.5f;
        g_x1[o] = bx[0] - hx; g_x2[o] = bx[0] + hx;
        g_y1[o] = bx[1] - hy; g_y2[o] = bx[1] + hy;
        g_ar[o] = bx[3] * bx[4];
    }
}

// ---------------- K5: suppression bitmask rows (32-col chunks) ------------
// thread = (batch b, row i, 32-column chunk c): 4*1024*32 = 131072 threads.
__global__ void k_iou() {
    int tid = blockIdx.x * blockDim.x + threadIdx.x;
    if (tid >= NBATCH * PREK * 32) return;
    int b   = tid >> 15;          // /(1024*32)
    int rem = tid & 32767;
    int i   = rem >> 5;
    int c   = rem & 31;           // 32-column chunk
    int o = b * PREK;
    int j0 = c * 32;
    unsigned w = 0;
    if (j0 + 31 > i) {            // chunk has at least one j > i
        float x1 = g_x1[o + i], x2 = g_x2[o + i];
        float y1 = g_y1[o + i], y2 = g_y2[o + i], ar = g_ar[o + i];
#pragma unroll 8
        for (int jj = 0; jj < 32; jj++) {
            int j = j0 + jj;
            if (j <= i) continue;
            float ix = fmaxf(fminf(x2, g_x2[o + j]) - fmaxf(x1, g_x1[o + j]), 0.f);
            float iy = fmaxf(fminf(y2, g_y2[o + j]) - fmaxf(y1, g_y1[o + j]), 0.f);
            float inter = ix * iy;
            float uni = ar + g_ar[o + j] - inter;
            float iou = inter / fmaxf(uni, 1e-6f);
            if (iou > 0.1f) w |= 1u << jj;
        }
    }
    g_rows[((size_t)(o + i)) * 32 + c] = w;
    if (w)
        atomicOr(&g_rowAny[b * 32 + (i >> 5)], 1u << (i & 31));
}

// ---------------- K6: sparse sequential NMS scan + output -----------------
__global__ __launch_bounds__(1024) void k_nms_out(float* __restrict__ out, int out_size) {
    __shared__ unsigned supp[32];
    int b = blockIdx.x, t = threadIdx.x;
    if (t < 32) {
        unsigned sup = 0;
        unsigned myAny = g_rowAny[b * 32 + t];
        for (int w = 0; w < 32; w++) {
            unsigned aw = __shfl_sync(0xffffffffu, myAny, w);
            while (aw) {
                int bit = __ffs(aw) - 1;
                aw &= aw - 1;
                int i = w * 32 + bit;
                unsigned sw = __shfl_sync(0xffffffffu, sup, i >> 5);
                if (!((sw >> (i & 31)) & 1u))
                    sup |= g_rows[((size_t)(b * PREK + i)) * 32 + t];
            }
        }
        supp[t] = sup;
    }
    __syncthreads();
    int o = b * PREK + t;
    float val = g_vals[o];
    bool valid = val > -5e8f;
    bool kp = valid && !((supp[t >> 5] >> (t & 31)) & 1u);
    float m = kp ? 1.f : 0.f;
    size_t base = (size_t)o * 8;
#pragma unroll
    for (int c = 0; c < 7; c++)
        if ((int)(base + c) < out_size) out[base + c] = g_box7[o * 7 + c] * m;
    if ((int)(base + 7) < out_size) out[base + 7] = val * m;
    size_t lbOff = (size_t)NBATCH * PREK * 8 + o;
    if ((int)lbOff < out_size) out[lbOff] = 0.f;
    size_t kpOff = (size_t)NBATCH * PREK * 9 + o;
    if ((int)kpOff < out_size) out[kpOff] = m;
}

// ---------------- launch ----------------
extern "C" void kernel_launch(void* const* d_in, const int* in_sizes, int n_in,
                              void* d_out, int out_size) {
    const float* feat = (const float*)d_in[0];
    const int*   bidx = (const int*)  d_in[1];
    const int*   coor = (const int*)  d_in[2];
    const float* Wc   = (const float*)d_in[3];
    const float* bc   = (const float*)d_in[4];
    const float* Wr   = (const float*)d_in[5];
    const float* br   = (const float*)d_in[6];
    int n = in_sizes[1];

    k_zero   <<<NBATCH * NBUCK / 256, 256>>>();
    k_gemv   <<<1480, 256>>>(feat, Wc, Wr, bc, br, bidx, coor, n);
    k_cutoff <<<NBATCH, 256>>>();
    k_compact<<<((n + 3) / 4 + 255) / 256, 256>>>(bidx, n);
    k_sort   <<<NBATCH, 1024>>>(n);
    k_iou    <<<(NBATCH * PREK * 32 + 255) / 256, 256>>>();
    k_nms_out<<<NBATCH, 1024>>>((float*)d_out, out_size);
}

// round 9
// speedup vs baseline: 1.2067x; 1.1966x over previous
#include <cuda_runtime.h>
#include <stdint.h>
#include <math.h>

// Problem constants
#define NBATCH 4
#define PREK   1024
#define NBUCK  65536      // 16-bit buckets of float bits (scores are positive)
#define CAP    2048       // candidate capacity per batch
#define MAXN   262144     // >= 200000
#define NEGBIG (-1e9f)

// ---------------- device scratch (no allocations allowed) ----------------
__device__ float              g_raw[MAXN * 12];           // raw head outputs (11 used)
__device__ float              g_boxes[MAXN * 8];          // decoded boxes (7 used)
__device__ unsigned           g_sbits[MAXN];              // score as ordered uint
__device__ int                g_hist[NBATCH * NBUCK];     // per-batch histogram
__device__ int                g_cut[NBATCH];              // cutoff bucket
__device__ int                g_cnt[NBATCH];              // candidate counters
__device__ unsigned long long g_cand[NBATCH * CAP];       // (score_bits<<32)|(~idx)
__device__ float              g_vals[NBATCH * PREK];      // top-k scores
__device__ float              g_box7[NBATCH * PREK * 7];  // gathered boxes
__device__ float              g_x1[NBATCH * PREK], g_x2[NBATCH * PREK];
__device__ float              g_y1[NBATCH * PREK], g_y2[NBATCH * PREK];
__device__ float              g_ar[NBATCH * PREK];
__device__ unsigned           g_rows[NBATCH * PREK * 32]; // suppression bitmask rows
__device__ unsigned           g_rowAny[NBATCH * 32];      // rows with any overlap

// ---------------- K0: zero scratch ----------------------------------------
__global__ void k_zero() {
    int i = blockIdx.x * blockDim.x + threadIdx.x;
    if (i < NBATCH * NBUCK) g_hist[i] = 0;
    if (i < NBATCH)         g_cnt[i]  = 0;
    if (i < NBATCH * 32)    g_rowAny[i] = 0;
}

// ---------------- K1: GEMV only, 2 points/warp (R6-exact, 103.5us) --------
// Per-lane partial: 8 sequential FMAs over features [8L,8L+8) (R1 order).
// Level-16 via exchange SHFL, levels 8,4,2,1 via xor butterfly in halves.
// Bitwise-identical to all passing rounds. No decode in the hot loop.
__global__ __launch_bounds__(256) void k_gemv(
    const float* __restrict__ feat,
    const float* __restrict__ Wc, const float* __restrict__ Wr, int n)
{
    int lane  = threadIdx.x & 31;
    int warp  = (blockIdx.x * blockDim.x + threadIdx.x) >> 5;
    int nwarp = (gridDim.x * blockDim.x) >> 5;
    int c0 = lane * 8;

    float w[11][8];
#pragma unroll
    for (int i = 0; i < 8; i++) {
        w[0][i] = Wc[(c0 + i) * 2 + 0];
        w[1][i] = Wc[(c0 + i) * 2 + 1];
#pragma unroll
        for (int o = 0; o < 9; o++) w[2 + o][i] = Wr[(c0 + i) * 9 + o];
    }

    bool hi = (lane & 16) != 0;
    int  oo = lane & 15;
    int npair = (n + 1) >> 1;

    int pr = warp;
    if (pr >= npair) return;

    int pA = 2 * pr, pBs = (pA + 1 < n) ? pA + 1 : pA;
    float4 A0 = *reinterpret_cast<const float4*>(feat + (size_t)pA  * 256 + c0);
    float4 A1 = *reinterpret_cast<const float4*>(feat + (size_t)pA  * 256 + c0 + 4);
    float4 B0 = *reinterpret_cast<const float4*>(feat + (size_t)pBs * 256 + c0);
    float4 B1 = *reinterpret_cast<const float4*>(feat + (size_t)pBs * 256 + c0 + 4);

    while (pr < npair) {
        int prn = pr + nwarp;
        float4 An0, An1, Bn0, Bn1;
        if (prn < npair) {               // prefetch next pair
            int qA = 2 * prn, qB = (qA + 1 < n) ? qA + 1 : qA;
            An0 = *reinterpret_cast<const float4*>(feat + (size_t)qA * 256 + c0);
            An1 = *reinterpret_cast<const float4*>(feat + (size_t)qA * 256 + c0 + 4);
            Bn0 = *reinterpret_cast<const float4*>(feat + (size_t)qB * 256 + c0);
            Bn1 = *reinterpret_cast<const float4*>(feat + (size_t)qB * 256 + c0 + 4);
        }

        float fvA[8] = {A0.x, A0.y, A0.z, A0.w, A1.x, A1.y, A1.z, A1.w};
        float fvB[8] = {B0.x, B0.y, B0.z, B0.w, B1.x, B1.y, B1.z, B1.w};

        float aA[11], aB[11];
#pragma unroll
        for (int o = 0; o < 11; o++) { aA[o] = 0.f; aB[o] = 0.f; }
#pragma unroll
        for (int i = 0; i < 8; i++)
#pragma unroll
            for (int o = 0; o < 11; o++) {
                aA[o] += fvA[i] * w[o][i];
                aB[o] += fvB[i] * w[o][i];
            }

        float cur[11];
#pragma unroll
        for (int o = 0; o < 11; o++) {
            float v = hi ? aA[o] : aB[o];
            float r = __shfl_xor_sync(0xffffffffu, v, 16);
            float mine = hi ? aB[o] : aA[o];
            cur[o] = mine + r;
        }
#pragma unroll
        for (int off = 8; off >= 1; off >>= 1)
#pragma unroll
            for (int o = 0; o < 11; o++)
                cur[o] += __shfl_xor_sync(0xffffffffu, cur[o], off);

        float val = cur[0];
#pragma unroll
        for (int o = 1; o < 11; o++) val = (oo == o) ? cur[o] : val;
        int p = 2 * pr + (hi ? 1 : 0);
        if (oo < 11 && p < n) g_raw[(size_t)p * 12 + oo] = val;

        pr = prn;
        A0 = An0; A1 = An1; B0 = Bn0; B1 = Bn1;
    }
}

// ---------------- K1b: decode + score + histogram (thread per point) ------
__global__ __launch_bounds__(256) void k_decode(
    const int* __restrict__ bidx, const int* __restrict__ coor,
    const float* __restrict__ bc, const float* __restrict__ br, int n)
{
    int p = blockIdx.x * blockDim.x + threadIdx.x;
    if (p >= n) return;
    const float4* r4 = reinterpret_cast<const float4*>(g_raw + (size_t)p * 12);
    float4 Ra = r4[0], Rb = r4[1], Rc = r4[2];

    float l0 = Ra.x + bc[0], l1 = Ra.y + bc[1];
    float conf = 1.f / (1.f + expf(l0 - l1));
    float r0 = Ra.z + br[0], r1 = Ra.w + br[1], r2 = Rb.x + br[2];
    float r3 = Rb.y + br[3], r4v = Rb.z + br[4], r5 = Rb.w + br[5];
    float r6 = Rc.x + br[6], r7 = Rc.y + br[7], r8 = Rc.z + br[8];
    float scr = 1.f / (1.f + expf(-r8));
    float score = conf * scr;

    float cx = (float)coor[2 * p]     * 0.8f + r0;
    float cy = (float)coor[2 * p + 1] * 0.8f + r1;
    float L  = expf(fminf(fmaxf(r3,  -6.f), 6.f));
    float Wd = expf(fminf(fmaxf(r4v, -6.f), 6.f));
    float H  = expf(fminf(fmaxf(r5,  -6.f), 6.f));
    float ang = atan2f(r6, r7);

    float4* b4 = reinterpret_cast<float4*>(g_boxes + (size_t)p * 8);
    b4[0] = make_float4(cx, cy, r2, L);
    b4[1] = make_float4(Wd, H, ang, 0.f);

    unsigned sb = __float_as_uint(score);
    g_sbits[p] = sb;
    atomicAdd(&g_hist[bidx[p] * NBUCK + (sb >> 16)], 1);
}

// ---------------- K2: per-batch cutoff bucket from histogram --------------
__global__ __launch_bounds__(256) void k_cutoff() {
    int b = blockIdx.x, t = threadIdx.x;
    const int4* h4 = reinterpret_cast<const int4*>(g_hist + b * NBUCK + t * 256);
    int s = 0;
#pragma unroll 8
    for (int i = 0; i < 64; i++) { int4 v = h4[i]; s += v.x + v.y + v.z + v.w; }
    __shared__ int cs[256];
    __shared__ int Sarr[257];
    cs[t] = s;
    __syncthreads();
    int S = 0;
    for (int u = t; u < 256; u++) S += cs[u];
    Sarr[t] = S;
    if (t == 0) Sarr[256] = 0;
    __syncthreads();
    if (S >= PREK && Sarr[t + 1] < PREK) {
        int running = Sarr[t + 1];
        int cut = t * 256;
        for (int bk = t * 256 + 255; bk >= t * 256; --bk) {
            running += g_hist[b * NBUCK + bk];
            if (running >= PREK) { cut = bk; break; }
        }
        g_cut[b] = cut;
    }
    if (t == 0 && Sarr[0] < PREK) g_cut[b] = 0;
}

// ---------------- K3: compact candidates >= cutoff bucket (x4 vec) --------
__global__ void k_compact(const int* __restrict__ bidx, int n) {
    int q = blockIdx.x * blockDim.x + threadIdx.x;
    int i0 = q * 4;
    if (i0 >= n) return;
    if (i0 + 3 < n) {
        int4 bv = *reinterpret_cast<const int4*>(bidx + i0);
        uint4 sv = *reinterpret_cast<const uint4*>(g_sbits + i0);
        int bb[4] = {bv.x, bv.y, bv.z, bv.w};
        unsigned ss[4] = {sv.x, sv.y, sv.z, sv.w};
#pragma unroll
        for (int k = 0; k < 4; k++) {
            if ((int)(ss[k] >> 16) >= g_cut[bb[k]]) {
                int pos = atomicAdd(&g_cnt[bb[k]], 1);
                if (pos < CAP)
                    g_cand[bb[k] * CAP + pos] =
                        ((unsigned long long)ss[k] << 32) |
                        (unsigned long long)(0xFFFFFFFFu - (unsigned)(i0 + k));
            }
        }
    } else {
        for (int i = i0; i < n; i++) {
            int b = bidx[i];
            unsigned sb = g_sbits[i];
            if ((int)(sb >> 16) >= g_cut[b]) {
                int pos = atomicAdd(&g_cnt[b], 1);
                if (pos < CAP)
                    g_cand[b * CAP + pos] =
                        ((unsigned long long)sb << 32) |
                        (unsigned long long)(0xFFFFFFFFu - (unsigned)i);
            }
        }
    }
}

// ---------------- K4: per-batch bitonic sort + gather top-1024 ------------
__global__ __launch_bounds__(1024) void k_sort(int n) {
    __shared__ unsigned long long sk[CAP];
    int b = blockIdx.x, t = threadIdx.x;
    int cnt = g_cnt[b]; if (cnt > CAP) cnt = CAP;
#pragma unroll
    for (int r = 0; r < CAP / 1024; r++) {
        int i = t + r * 1024;
        sk[i] = (i < cnt) ? g_cand[b * CAP + i] : 0ULL;
    }
    __syncthreads();
    for (int k = 2; k <= CAP; k <<= 1) {
        for (int j = k >> 1; j > 0; j >>= 1) {
#pragma unroll
            for (int r = 0; r < CAP / 1024; r++) {
                int i = t + r * 1024;
                int l = i ^ j;
                if (l > i) {
                    unsigned long long A = sk[i], B = sk[l];
                    bool desc = ((i & k) == 0);
                    if (desc ? (A < B) : (A > B)) { sk[i] = B; sk[l] = A; }
                }
            }
            __syncthreads();
        }
    }
    if (t < PREK) {
        unsigned long long key = sk[t];
        unsigned idx = 0xFFFFFFFFu - (unsigned)(key & 0xFFFFFFFFull);
        float val = __uint_as_float((unsigned)(key >> 32));
        bool ok = (key != 0ULL) && (idx < (unsigned)n);
        float bx[7];
        if (ok) {
            const float4* p4 = reinterpret_cast<const float4*>(g_boxes + (size_t)idx * 8);
            float4 A = p4[0], B = p4[1];
            bx[0] = A.x; bx[1] = A.y; bx[2] = A.z; bx[3] = A.w;
            bx[4] = B.x; bx[5] = B.y; bx[6] = B.z;
        } else {
#pragma unroll
            for (int c = 0; c < 7; c++) bx[c] = 0.f;
            val = NEGBIG;
        }
        int o = b * PREK + t;
        g_vals[o] = val;
#pragma unroll
        for (int c = 0; c < 7; c++) g_box7[o * 7 + c] = bx[c];
        float hx = bx[3] * 0.5f, hy = bx[4] * 0.5f;
        g_x1[o] = bx[0] - hx; g_x2[o] = bx[0] + hx;
        g_y1[o] = bx[1] - hy; g_y2[o] = bx[1] + hy;
        g_ar[o] = bx[3] * bx[4];
    }
}

// ---------------- K5: suppression bitmask rows (32-col chunks) ------------
__global__ void k_iou() {
    int tid = blockIdx.x * blockDim.x + threadIdx.x;
    if (tid >= NBATCH * PREK * 32) return;
    int b   = tid >> 15;
    int rem = tid & 32767;
    int i   = rem >> 5;
    int c   = rem & 31;
    int o = b * PREK;
    int j0 = c * 32;
    unsigned w = 0;
    if (j0 + 31 > i) {
        float x1 = g_x1[o + i], x2 = g_x2[o + i];
        float y1 = g_y1[o + i], y2 = g_y2[o + i], ar = g_ar[o + i];
#pragma unroll 8
        for (int jj = 0; jj < 32; jj++) {
            int j = j0 + jj;
            if (j <= i) continue;
            float ix = fmaxf(fminf(x2, g_x2[o + j]) - fmaxf(x1, g_x1[o + j]), 0.f);
            float iy = fmaxf(fminf(y2, g_y2[o + j]) - fmaxf(y1, g_y1[o + j]), 0.f);
            float inter = ix * iy;
            float uni = ar + g_ar[o + j] - inter;
            float iou = inter / fmaxf(uni, 1e-6f);
            if (iou > 0.1f) w |= 1u << jj;
        }
    }
    g_rows[((size_t)(o + i)) * 32 + c] = w;
    if (w)
        atomicOr(&g_rowAny[b * 32 + (i >> 5)], 1u << (i & 31));
}

// ---------------- K6: sparse sequential NMS scan + output -----------------
__global__ __launch_bounds__(1024) void k_nms_out(float* __restrict__ out, int out_size) {
    __shared__ unsigned supp[32];
    int b = blockIdx.x, t = threadIdx.x;
    if (t < 32) {
        unsigned sup = 0;
        unsigned myAny = g_rowAny[b * 32 + t];
        for (int w = 0; w < 32; w++) {
            unsigned aw = __shfl_sync(0xffffffffu, myAny, w);
            while (aw) {
                int bit = __ffs(aw) - 1;
                aw &= aw - 1;
                int i = w * 32 + bit;
                unsigned sw = __shfl_sync(0xffffffffu, sup, i >> 5);
                if (!((sw >> (i & 31)) & 1u))
                    sup |= g_rows[((size_t)(b * PREK + i)) * 32 + t];
            }
        }
        supp[t] = sup;
    }
    __syncthreads();
    int o = b * PREK + t;
    float val = g_vals[o];
    bool valid = val > -5e8f;
    bool kp = valid && !((supp[t >> 5] >> (t & 31)) & 1u);
    float m = kp ? 1.f : 0.f;
    size_t base = (size_t)o * 8;
#pragma unroll
    for (int c = 0; c < 7; c++)
        if ((int)(base + c) < out_size) out[base + c] = g_box7[o * 7 + c] * m;
    if ((int)(base + 7) < out_size) out[base + 7] = val * m;
    size_t lbOff = (size_t)NBATCH * PREK * 8 + o;
    if ((int)lbOff < out_size) out[lbOff] = 0.f;
    size_t kpOff = (size_t)NBATCH * PREK * 9 + o;
    if ((int)kpOff < out_size) out[kpOff] = m;
}

// ---------------- launch ----------------
extern "C" void kernel_launch(void* const* d_in, const int* in_sizes, int n_in,
                              void* d_out, int out_size) {
    const float* feat = (const float*)d_in[0];
    const int*   bidx = (const int*)  d_in[1];
    const int*   coor = (const int*)  d_in[2];
    const float* Wc   = (const float*)d_in[3];
    const float* bc   = (const float*)d_in[4];
    const float* Wr   = (const float*)d_in[5];
    const float* br   = (const float*)d_in[6];
    int n = in_sizes[1];

    k_zero   <<<NBATCH * NBUCK / 256, 256>>>();
    k_gemv   <<<1480, 256>>>(feat, Wc, Wr, n);
    k_decode <<<(n + 255) / 256, 256>>>(bidx, coor, bc, br, n);
    k_cutoff <<<NBATCH, 256>>>();
    k_compact<<<((n + 3) / 4 + 255) / 256, 256>>>(bidx, n);
    k_sort   <<<NBATCH, 1024>>>(n);
    k_iou    <<<(NBATCH * PREK * 32 + 255) / 256, 256>>>();
    k_nms_out<<<NBATCH, 1024>>>((float*)d_out, out_size);
}

// round 10
// speedup vs baseline: 1.4827x; 1.2287x over previous
#include <cuda_runtime.h>
#include <stdint.h>
#include <math.h>

// Problem constants
#define NBATCH 4
#define PREK   1024
#define NBUCK  65536      // 16-bit buckets of float bits (scores are positive)
#define CAP    2048       // candidate capacity per batch
#define MAXN   262144     // >= 200000
#define NEGBIG (-1e9f)

// ---------------- device scratch (no allocations allowed) ----------------
__device__ float              g_raw[MAXN * 12];           // raw head outputs (11 used)
__device__ float              g_boxes[MAXN * 8];          // decoded boxes (7 used)
__device__ unsigned           g_sbits[MAXN];              // score as ordered uint
__device__ int                g_hist[NBATCH * NBUCK];     // per-batch histogram
__device__ int                g_cut[NBATCH];              // cutoff bucket
__device__ int                g_cnt[NBATCH];              // candidate counters
__device__ unsigned long long g_cand[NBATCH * CAP];       // (score_bits<<32)|(~idx)
__device__ float              g_vals[NBATCH * PREK];      // top-k scores
__device__ float              g_box7[NBATCH * PREK * 7];  // gathered boxes
__device__ float              g_x1[NBATCH * PREK], g_x2[NBATCH * PREK];
__device__ float              g_y1[NBATCH * PREK], g_y2[NBATCH * PREK];
__device__ float              g_ar[NBATCH * PREK];
__device__ unsigned           g_rows[NBATCH * PREK * 32]; // suppression bitmask rows
__device__ unsigned           g_rowAny[NBATCH * 32];      // rows with any overlap

// ---------------- K1: GEMV, 2 points/warp (R6-measured 103.5us) -----------
// Bitwise-frozen math. Also zeroes scratch (fused, R4-style).
__global__ __launch_bounds__(256) void k_gemv(
    const float* __restrict__ feat,
    const float* __restrict__ Wc, const float* __restrict__ Wr, int n)
{
    int gtid = blockIdx.x * blockDim.x + threadIdx.x;
    if (gtid < NBATCH * NBUCK) g_hist[gtid] = 0;
    if (gtid < NBATCH)         g_cnt[gtid]  = 0;
    if (gtid < NBATCH * 32)    g_rowAny[gtid] = 0;

    int lane  = threadIdx.x & 31;
    int warp  = gtid >> 5;
    int nwarp = (gridDim.x * blockDim.x) >> 5;
    int c0 = lane * 8;

    float w[11][8];
#pragma unroll
    for (int i = 0; i < 8; i++) {
        w[0][i] = Wc[(c0 + i) * 2 + 0];
        w[1][i] = Wc[(c0 + i) * 2 + 1];
#pragma unroll
        for (int o = 0; o < 9; o++) w[2 + o][i] = Wr[(c0 + i) * 9 + o];
    }

    bool hi = (lane & 16) != 0;
    int  oo = lane & 15;
    int npair = (n + 1) >> 1;

    int pr = warp;
    if (pr >= npair) return;

    int pA = 2 * pr, pBs = (pA + 1 < n) ? pA + 1 : pA;
    float4 A0 = *reinterpret_cast<const float4*>(feat + (size_t)pA  * 256 + c0);
    float4 A1 = *reinterpret_cast<const float4*>(feat + (size_t)pA  * 256 + c0 + 4);
    float4 B0 = *reinterpret_cast<const float4*>(feat + (size_t)pBs * 256 + c0);
    float4 B1 = *reinterpret_cast<const float4*>(feat + (size_t)pBs * 256 + c0 + 4);

    while (pr < npair) {
        int prn = pr + nwarp;
        float4 An0, An1, Bn0, Bn1;
        if (prn < npair) {               // prefetch next pair
            int qA = 2 * prn, qB = (qA + 1 < n) ? qA + 1 : qA;
            An0 = *reinterpret_cast<const float4*>(feat + (size_t)qA * 256 + c0);
            An1 = *reinterpret_cast<const float4*>(feat + (size_t)qA * 256 + c0 + 4);
            Bn0 = *reinterpret_cast<const float4*>(feat + (size_t)qB * 256 + c0);
            Bn1 = *reinterpret_cast<const float4*>(feat + (size_t)qB * 256 + c0 + 4);
        }

        float fvA[8] = {A0.x, A0.y, A0.z, A0.w, A1.x, A1.y, A1.z, A1.w};
        float fvB[8] = {B0.x, B0.y, B0.z, B0.w, B1.x, B1.y, B1.z, B1.w};

        float aA[11], aB[11];
#pragma unroll
        for (int o = 0; o < 11; o++) { aA[o] = 0.f; aB[o] = 0.f; }
#pragma unroll
        for (int i = 0; i < 8; i++)
#pragma unroll
            for (int o = 0; o < 11; o++) {
                aA[o] += fvA[i] * w[o][i];
                aB[o] += fvB[i] * w[o][i];
            }

        float cur[11];
#pragma unroll
        for (int o = 0; o < 11; o++) {
            float v = hi ? aA[o] : aB[o];
            float r = __shfl_xor_sync(0xffffffffu, v, 16);
            float mine = hi ? aB[o] : aA[o];
            cur[o] = mine + r;
        }
#pragma unroll
        for (int off = 8; off >= 1; off >>= 1)
#pragma unroll
            for (int o = 0; o < 11; o++)
                cur[o] += __shfl_xor_sync(0xffffffffu, cur[o], off);

        float val = cur[0];
#pragma unroll
        for (int o = 1; o < 11; o++) val = (oo == o) ? cur[o] : val;
        int p = 2 * pr + (hi ? 1 : 0);
        if (oo < 11 && p < n) g_raw[(size_t)p * 12 + oo] = val;

        pr = prn;
        A0 = An0; A1 = An1; B0 = Bn0; B1 = Bn1;
    }
}

// ---------------- K1b: decode + score + histogram (thread per point) ------
__global__ __launch_bounds__(256) void k_decode(
    const int* __restrict__ bidx, const int* __restrict__ coor,
    const float* __restrict__ bc, const float* __restrict__ br, int n)
{
    int p = blockIdx.x * blockDim.x + threadIdx.x;
    if (p >= n) return;
    const float4* r4 = reinterpret_cast<const float4*>(g_raw + (size_t)p * 12);
    float4 Ra = r4[0], Rb = r4[1], Rc = r4[2];

    float l0 = Ra.x + bc[0], l1 = Ra.y + bc[1];
    float conf = 1.f / (1.f + expf(l0 - l1));
    float r0 = Ra.z + br[0], r1 = Ra.w + br[1], r2 = Rb.x + br[2];
    float r3 = Rb.y + br[3], r4v = Rb.z + br[4], r5 = Rb.w + br[5];
    float r6 = Rc.x + br[6], r7 = Rc.y + br[7], r8 = Rc.z + br[8];
    float scr = 1.f / (1.f + expf(-r8));
    float score = conf * scr;

    float cx = (float)coor[2 * p]     * 0.8f + r0;
    float cy = (float)coor[2 * p + 1] * 0.8f + r1;
    float L  = expf(fminf(fmaxf(r3,  -6.f), 6.f));
    float Wd = expf(fminf(fmaxf(r4v, -6.f), 6.f));
    float H  = expf(fminf(fmaxf(r5,  -6.f), 6.f));
    float ang = atan2f(r6, r7);

    float4* b4 = reinterpret_cast<float4*>(g_boxes + (size_t)p * 8);
    b4[0] = make_float4(cx, cy, r2, L);
    b4[1] = make_float4(Wd, H, ang, 0.f);

    unsigned sb = __float_as_uint(score);
    g_sbits[p] = sb;
    atomicAdd(&g_hist[bidx[p] * NBUCK + (sb >> 16)], 1);
}

// ---------------- K2: cutoff v2 — fully parallel suffix scans -------------
__global__ __launch_bounds__(256) void k_cutoff() {
    __shared__ int sc[2][256];
    __shared__ int sAbove;     // suffix-exclusive above winning chunk
    __shared__ int sChunk;     // winning chunk index
    int b = blockIdx.x, t = threadIdx.x;

    // per-thread chunk sum (256 buckets each)
    const int4* h4 = reinterpret_cast<const int4*>(g_hist + b * NBUCK + t * 256);
    int s = 0;
#pragma unroll 8
    for (int i = 0; i < 64; i++) { int4 v = h4[i]; s += v.x + v.y + v.z + v.w; }

    // Hillis-Steele inclusive SUFFIX scan over 256 chunk sums
    int cur = 0, nxt = 1;
    sc[cur][t] = s;
    __syncthreads();
#pragma unroll
    for (int d = 1; d < 256; d <<= 1) {
        int v = sc[cur][t] + ((t + d < 256) ? sc[cur][t + d] : 0);
        sc[nxt][t] = v;
        __syncthreads();
        cur ^= 1; nxt ^= 1;
    }
    int Sincl = sc[cur][t];                               // sum over chunks >= t
    int Sexcl = (t + 1 < 256) ? sc[cur][t + 1] : 0;       // sum over chunks >  t

    if (t == 0 && Sincl < PREK) { sChunk = 0; sAbove = 0; }  // degenerate
    if (Sincl >= PREK && Sexcl < PREK) { sChunk = t; sAbove = Sexcl; }
    __syncthreads();

    // parallel scan of the winning chunk's 256 buckets
    int chunk = sChunk, above = sAbove;
    int h = g_hist[b * NBUCK + chunk * 256 + t];
    sc[cur][t] = h;
    __syncthreads();
#pragma unroll
    for (int d = 1; d < 256; d <<= 1) {
        int v = sc[cur][t] + ((t + d < 256) ? sc[cur][t + d] : 0);
        sc[nxt][t] = v;
        __syncthreads();
        cur ^= 1; nxt ^= 1;
    }
    int inclK = above + sc[cur][t];                        // total for buckets >= this one
    int exclK = above + ((t + 1 < 256) ? sc[cur][t + 1] : 0);
    // cut = highest bucket where cumulative-from-top >= PREK
    if (inclK >= PREK && exclK < PREK) g_cut[b] = chunk * 256 + t;
    if (t == 0 && above + sc[cur][0] < PREK) g_cut[b] = chunk * 256;  // < PREK total
}

// ---------------- K3: compact candidates >= cutoff bucket (x4 vec) --------
__global__ void k_compact(const int* __restrict__ bidx, int n) {
    int q = blockIdx.x * blockDim.x + threadIdx.x;
    int i0 = q * 4;
    if (i0 >= n) return;
    if (i0 + 3 < n) {
        int4 bv = *reinterpret_cast<const int4*>(bidx + i0);
        uint4 sv = *reinterpret_cast<const uint4*>(g_sbits + i0);
        int bb[4] = {bv.x, bv.y, bv.z, bv.w};
        unsigned ss[4] = {sv.x, sv.y, sv.z, sv.w};
#pragma unroll
        for (int k = 0; k < 4; k++) {
            if ((int)(ss[k] >> 16) >= g_cut[bb[k]]) {
                int pos = atomicAdd(&g_cnt[bb[k]], 1);
                if (pos < CAP)
                    g_cand[bb[k] * CAP + pos] =
                        ((unsigned long long)ss[k] << 32) |
                        (unsigned long long)(0xFFFFFFFFu - (unsigned)(i0 + k));
            }
        }
    } else {
        for (int i = i0; i < n; i++) {
            int b = bidx[i];
            unsigned sb = g_sbits[i];
            if ((int)(sb >> 16) >= g_cut[b]) {
                int pos = atomicAdd(&g_cnt[b], 1);
                if (pos < CAP)
                    g_cand[b * CAP + pos] =
                        ((unsigned long long)sb << 32) |
                        (unsigned long long)(0xFFFFFFFFu - (unsigned)i);
            }
        }
    }
}

// ---------------- K4: per-batch bitonic sort + gather top-1024 ------------
__global__ __launch_bounds__(1024) void k_sort(int n) {
    __shared__ unsigned long long sk[CAP];
    int b = blockIdx.x, t = threadIdx.x;
    int cnt = g_cnt[b]; if (cnt > CAP) cnt = CAP;
#pragma unroll
    for (int r = 0; r < CAP / 1024; r++) {
        int i = t + r * 1024;
        sk[i] = (i < cnt) ? g_cand[b * CAP + i] : 0ULL;
    }
    __syncthreads();
    for (int k = 2; k <= CAP; k <<= 1) {
        for (int j = k >> 1; j > 0; j >>= 1) {
#pragma unroll
            for (int r = 0; r < CAP / 1024; r++) {
                int i = t + r * 1024;
                int l = i ^ j;
                if (l > i) {
                    unsigned long long A = sk[i], B = sk[l];
                    bool desc = ((i & k) == 0);
                    if (desc ? (A < B) : (A > B)) { sk[i] = B; sk[l] = A; }
                }
            }
            __syncthreads();
        }
    }
    if (t < PREK) {
        unsigned long long key = sk[t];
        unsigned idx = 0xFFFFFFFFu - (unsigned)(key & 0xFFFFFFFFull);
        float val = __uint_as_float((unsigned)(key >> 32));
        bool ok = (key != 0ULL) && (idx < (unsigned)n);
        float bx[7];
        if (ok) {
            const float4* p4 = reinterpret_cast<const float4*>(g_boxes + (size_t)idx * 8);
            float4 A = p4[0], B = p4[1];
            bx[0] = A.x; bx[1] = A.y; bx[2] = A.z; bx[3] = A.w;
            bx[4] = B.x; bx[5] = B.y; bx[6] = B.z;
        } else {
#pragma unroll
            for (int c = 0; c < 7; c++) bx[c] = 0.f;
            val = NEGBIG;
        }
        int o = b * PREK + t;
        g_vals[o] = val;
#pragma unroll
        for (int c = 0; c < 7; c++) g_box7[o * 7 + c] = bx[c];
        float hx = bx[3] * 0.5f, hy = bx[4] * 0.5f;
        g_x1[o] = bx[0] - hx; g_x2[o] = bx[0] + hx;
        g_y1[o] = bx[1] - hy; g_y2[o] = bx[1] + hy;
        g_ar[o] = bx[3] * bx[4];
    }
}

// ---------------- K5: iou v2 — warp per (row, 32-col chunk), ballot -------
// lane = jj -> all j-loads coalesced; no inner loop.
__global__ __launch_bounds__(256) void k_iou() {
    int wtid = (blockIdx.x * blockDim.x + threadIdx.x) >> 5;
    int lane = threadIdx.x & 31;
    if (wtid >= NBATCH * PREK * 32) return;
    int b = wtid >> 15;
    int i = (wtid >> 5) & (PREK - 1);
    int c = wtid & 31;
    int o = b * PREK;
    int j = c * 32 + lane;

    unsigned w = 0;
    if (c * 32 + 31 > i) {                 // chunk contains some j > i
        float x1 = g_x1[o + i], x2 = g_x2[o + i];
        float y1 = g_y1[o + i], y2 = g_y2[o + i], ar = g_ar[o + i];
        bool hit = false;
        if (j > i) {
            float ix = fmaxf(fminf(x2, g_x2[o + j]) - fmaxf(x1, g_x1[o + j]), 0.f);
            float iy = fmaxf(fminf(y2, g_y2[o + j]) - fmaxf(y1, g_y1[o + j]), 0.f);
            float inter = ix * iy;
            float uni = ar + g_ar[o + j] - inter;
            hit = (inter / fmaxf(uni, 1e-6f)) > 0.1f;
        }
        w = __ballot_sync(0xffffffffu, hit);
    }
    if (lane == 0) {
        g_rows[((size_t)(o + i)) * 32 + c] = w;
        if (w) atomicOr(&g_rowAny[b * 32 + (i >> 5)], 1u << (i & 31));
    }
}

// ---------------- K6: sparse sequential NMS scan + output -----------------
__global__ __launch_bounds__(1024) void k_nms_out(float* __restrict__ out, int out_size) {
    __shared__ unsigned supp[32];
    int b = blockIdx.x, t = threadIdx.x;
    if (t < 32) {
        unsigned sup = 0;
        unsigned myAny = g_rowAny[b * 32 + t];
        for (int w = 0; w < 32; w++) {
            unsigned aw = __shfl_sync(0xffffffffu, myAny, w);
            while (aw) {
                int bit = __ffs(aw) - 1;
                aw &= aw - 1;
                int i = w * 32 + bit;
                unsigned sw = __shfl_sync(0xffffffffu, sup, i >> 5);
                if (!((sw >> (i & 31)) & 1u))
                    sup |= g_rows[((size_t)(b * PREK + i)) * 32 + t];
            }
        }
        supp[t] = sup;
    }
    __syncthreads();
    int o = b * PREK + t;
    float val = g_vals[o];
    bool valid = val > -5e8f;
    bool kp = valid && !((supp[t >> 5] >> (t & 31)) & 1u);
    float m = kp ? 1.f : 0.f;
    size_t base = (size_t)o * 8;
#pragma unroll
    for (int c = 0; c < 7; c++)
        if ((int)(base + c) < out_size) out[base + c] = g_box7[o * 7 + c] * m;
    if ((int)(base + 7) < out_size) out[base + 7] = val * m;
    size_t lbOff = (size_t)NBATCH * PREK * 8 + o;
    if ((int)lbOff < out_size) out[lbOff] = 0.f;
    size_t kpOff = (size_t)NBATCH * PREK * 9 + o;
    if ((int)kpOff < out_size) out[kpOff] = m;
}

// ---------------- launch ----------------
extern "C" void kernel_launch(void* const* d_in, const int* in_sizes, int n_in,
                              void* d_out, int out_size) {
    const float* feat = (const float*)d_in[0];
    const int*   bidx = (const int*)  d_in[1];
    const int*   coor = (const int*)  d_in[2];
    const float* Wc   = (const float*)d_in[3];
    const float* bc   = (const float*)d_in[4];
    const float* Wr   = (const float*)d_in[5];
    const float* br   = (const float*)d_in[6];
    int n = in_sizes[1];

    k_gemv   <<<1480, 256>>>(feat, Wc, Wr, n);   // also zeroes hist/cnt/rowAny
    k_decode <<<(n + 255) / 256, 256>>>(bidx, coor, bc, br, n);
    k_cutoff <<<NBATCH, 256>>>();
    k_compact<<<((n + 3) / 4 + 255) / 256, 256>>>(bidx, n);
    k_sort   <<<NBATCH, 1024>>>(n);
    k_iou    <<<(NBATCH * PREK * 32 * 32 + 255) / 256, 256>>>();
    k_nms_out<<<NBATCH, 1024>>>((float*)d_out, out_size);
}

// round 11
// speedup vs baseline: 1.8488x; 1.2469x over previous
#include <cuda_runtime.h>
#include <stdint.h>
#include <math.h>

// Problem constants
#define NBATCH 4
#define PREK   1024
#define NBUCK  65536      // 16-bit buckets of float bits (scores are positive)
#define CAP    2048       // candidate capacity per batch
#define MAXN   262144     // >= 200000
#define NEGBIG (-1e9f)

#define GEMV_BLOCKS 148   // single wave, 1 block/SM

// ---------------- device scratch (no allocations allowed) ----------------
__device__ float              g_raw[MAXN * 12];           // raw head outputs (11 used)
__device__ float              g_boxes[MAXN * 8];          // decoded boxes (7 used)
__device__ unsigned           g_sbits[MAXN];              // score as ordered uint
__device__ int                g_hist[NBATCH * NBUCK];     // per-batch histogram
__device__ int                g_cut[NBATCH];              // cutoff bucket
__device__ int                g_cnt[NBATCH];              // candidate counters
__device__ unsigned long long g_cand[NBATCH * CAP];       // (score_bits<<32)|(~idx)
__device__ float              g_vals[NBATCH * PREK];      // top-k scores
__device__ float              g_box7[NBATCH * PREK * 7];  // gathered boxes
__device__ float              g_x1[NBATCH * PREK], g_x2[NBATCH * PREK];
__device__ float              g_y1[NBATCH * PREK], g_y2[NBATCH * PREK];
__device__ float              g_ar[NBATCH * PREK];
__device__ unsigned           g_rows[NBATCH * PREK * 32]; // suppression bitmask rows
__device__ unsigned           g_rowAny[NBATCH * 32];      // rows with any overlap

// ---------------- packed f32x2 helpers (each half = independent fma.rn) ---
__device__ __forceinline__ unsigned long long pk2(float lo, float hi) {
    unsigned long long r;
    asm("mov.b64 %0, {%1, %2};" : "=l"(r) : "f"(lo), "f"(hi));
    return r;
}
__device__ __forceinline__ void upk2(unsigned long long v, float& lo, float& hi) {
    asm("mov.b64 {%0, %1}, %2;" : "=f"(lo), "=f"(hi) : "l"(v));
}
__device__ __forceinline__ unsigned long long ffma2(
    unsigned long long a, unsigned long long b, unsigned long long c) {
    unsigned long long d;
    asm("fma.rn.f32x2 %0, %1, %2, %3;" : "=l"(d) : "l"(a), "l"(b), "l"(c));
    return d;
}

// ---------------- K1: GEMV, 2 points/warp, packed-output FFMA2 ------------
// Each 32-bit half of a packed accumulator runs the EXACT scalar chain
// acc[o] += fv[i]*w[o][i] sequentially over i (R1 order) -> bitwise frozen.
// Exchange (off=16) + butterfly (8,4,2,1) verbatim from passing rounds.
// Also zeroes scratch counters in the prologue.
__global__ __launch_bounds__(256) void k_gemv(
    const float* __restrict__ feat,
    const float* __restrict__ Wc, const float* __restrict__ Wr, int n)
{
    int gtid   = blockIdx.x * blockDim.x + threadIdx.x;
    int stride = gridDim.x * blockDim.x;
    for (int i = gtid; i < NBATCH * NBUCK; i += stride) g_hist[i] = 0;
    if (gtid < NBATCH)      g_cnt[gtid]  = 0;
    if (gtid < NBATCH * 32) g_rowAny[gtid] = 0;

    int lane  = threadIdx.x & 31;
    int warp  = gtid >> 5;
    int nwarp = stride >> 5;
    int c0 = lane * 8;

    // packed weights: pairs (Wc0,Wc1),(Wr0,Wr1),(Wr2,Wr3),(Wr4,Wr5),(Wr6,Wr7),(Wr8,0)
    unsigned long long wp[6][8];
#pragma unroll
    for (int i = 0; i < 8; i++) {
        wp[0][i] = pk2(Wc[(c0 + i) * 2 + 0], Wc[(c0 + i) * 2 + 1]);
        wp[1][i] = pk2(Wr[(c0 + i) * 9 + 0], Wr[(c0 + i) * 9 + 1]);
        wp[2][i] = pk2(Wr[(c0 + i) * 9 + 2], Wr[(c0 + i) * 9 + 3]);
        wp[3][i] = pk2(Wr[(c0 + i) * 9 + 4], Wr[(c0 + i) * 9 + 5]);
        wp[4][i] = pk2(Wr[(c0 + i) * 9 + 6], Wr[(c0 + i) * 9 + 7]);
        wp[5][i] = pk2(Wr[(c0 + i) * 9 + 8], 0.f);
    }

    bool hi = (lane & 16) != 0;
    int  oo = lane & 15;
    int npair = (n + 1) >> 1;

    int pr = warp;
    if (pr >= npair) return;

    int pA = 2 * pr, pBs = (pA + 1 < n) ? pA + 1 : pA;
    float4 A0 = *reinterpret_cast<const float4*>(feat + (size_t)pA  * 256 + c0);
    float4 A1 = *reinterpret_cast<const float4*>(feat + (size_t)pA  * 256 + c0 + 4);
    float4 B0 = *reinterpret_cast<const float4*>(feat + (size_t)pBs * 256 + c0);
    float4 B1 = *reinterpret_cast<const float4*>(feat + (size_t)pBs * 256 + c0 + 4);

    while (pr < npair) {
        int prn = pr + nwarp;
        float4 An0, An1, Bn0, Bn1;
        if (prn < npair) {               // prefetch next pair
            int qA = 2 * prn, qB = (qA + 1 < n) ? qA + 1 : qA;
            An0 = *reinterpret_cast<const float4*>(feat + (size_t)qA * 256 + c0);
            An1 = *reinterpret_cast<const float4*>(feat + (size_t)qA * 256 + c0 + 4);
            Bn0 = *reinterpret_cast<const float4*>(feat + (size_t)qB * 256 + c0);
            Bn1 = *reinterpret_cast<const float4*>(feat + (size_t)qB * 256 + c0 + 4);
        }

        float fvA[8] = {A0.x, A0.y, A0.z, A0.w, A1.x, A1.y, A1.z, A1.w};
        float fvB[8] = {B0.x, B0.y, B0.z, B0.w, B1.x, B1.y, B1.z, B1.w};

        unsigned long long accA[6], accB[6];
#pragma unroll
        for (int g = 0; g < 6; g++) { accA[g] = 0ULL; accB[g] = 0ULL; }
#pragma unroll
        for (int i = 0; i < 8; i++) {
            unsigned long long fa = pk2(fvA[i], fvA[i]);
            unsigned long long fb = pk2(fvB[i], fvB[i]);
#pragma unroll
            for (int g = 0; g < 6; g++) {
                accA[g] = ffma2(fa, wp[g][i], accA[g]);
                accB[g] = ffma2(fb, wp[g][i], accB[g]);
            }
        }

        float aA[11], aB[11], dump;
        upk2(accA[0], aA[0], aA[1]);
        upk2(accA[1], aA[2], aA[3]);
        upk2(accA[2], aA[4], aA[5]);
        upk2(accA[3], aA[6], aA[7]);
        upk2(accA[4], aA[8], aA[9]);
        upk2(accA[5], aA[10], dump);
        upk2(accB[0], aB[0], aB[1]);
        upk2(accB[1], aB[2], aB[3]);
        upk2(accB[2], aB[4], aB[5]);
        upk2(accB[3], aB[6], aB[7]);
        upk2(accB[4], aB[8], aB[9]);
        upk2(accB[5], aB[10], dump);

        // exchange (off=16) + butterfly (8,4,2,1) — verbatim frozen
        float cur[11];
#pragma unroll
        for (int o = 0; o < 11; o++) {
            float v = hi ? aA[o] : aB[o];
            float r = __shfl_xor_sync(0xffffffffu, v, 16);
            float mine = hi ? aB[o] : aA[o];
            cur[o] = mine + r;
        }
#pragma unroll
        for (int off = 8; off >= 1; off >>= 1)
#pragma unroll
            for (int o = 0; o < 11; o++)
                cur[o] += __shfl_xor_sync(0xffffffffu, cur[o], off);

        float val = cur[0];
#pragma unroll
        for (int o = 1; o < 11; o++) val = (oo == o) ? cur[o] : val;
        int p = 2 * pr + (hi ? 1 : 0);
        if (oo < 11 && p < n) g_raw[(size_t)p * 12 + oo] = val;

        pr = prn;
        A0 = An0; A1 = An1; B0 = Bn0; B1 = Bn1;
    }
}

// ---------------- K1b: decode + score + histogram (thread per point) ------
__global__ __launch_bounds__(256) void k_decode(
    const int* __restrict__ bidx, const int* __restrict__ coor,
    const float* __restrict__ bc, const float* __restrict__ br, int n)
{
    int p = blockIdx.x * blockDim.x + threadIdx.x;
    if (p >= n) return;
    const float4* r4 = reinterpret_cast<const float4*>(g_raw + (size_t)p * 12);
    float4 Ra = r4[0], Rb = r4[1], Rc = r4[2];

    float l0 = Ra.x + bc[0], l1 = Ra.y + bc[1];
    float conf = 1.f / (1.f + expf(l0 - l1));
    float r0 = Ra.z + br[0], r1 = Ra.w + br[1], r2 = Rb.x + br[2];
    float r3 = Rb.y + br[3], r4v = Rb.z + br[4], r5 = Rb.w + br[5];
    float r6 = Rc.x + br[6], r7 = Rc.y + br[7], r8 = Rc.z + br[8];
    float scr = 1.f / (1.f + expf(-r8));
    float score = conf * scr;

    float cx = (float)coor[2 * p]     * 0.8f + r0;
    float cy = (float)coor[2 * p + 1] * 0.8f + r1;
    float L  = expf(fminf(fmaxf(r3,  -6.f), 6.f));
    float Wd = expf(fminf(fmaxf(r4v, -6.f), 6.f));
    float H  = expf(fminf(fmaxf(r5,  -6.f), 6.f));
    float ang = atan2f(r6, r7);

    float4* b4 = reinterpret_cast<float4*>(g_boxes + (size_t)p * 8);
    b4[0] = make_float4(cx, cy, r2, L);
    b4[1] = make_float4(Wd, H, ang, 0.f);

    unsigned sb = __float_as_uint(score);
    g_sbits[p] = sb;
    atomicAdd(&g_hist[bidx[p] * NBUCK + (sb >> 16)], 1);
}

// ---------------- K2: cutoff — fully parallel suffix scans ----------------
__global__ __launch_bounds__(256) void k_cutoff() {
    __shared__ int sc[2][256];
    __shared__ int sAbove;
    __shared__ int sChunk;
    int b = blockIdx.x, t = threadIdx.x;

    const int4* h4 = reinterpret_cast<const int4*>(g_hist + b * NBUCK + t * 256);
    int s = 0;
#pragma unroll 8
    for (int i = 0; i < 64; i++) { int4 v = h4[i]; s += v.x + v.y + v.z + v.w; }

    int cur = 0, nxt = 1;
    sc[cur][t] = s;
    __syncthreads();
#pragma unroll
    for (int d = 1; d < 256; d <<= 1) {
        int v = sc[cur][t] + ((t + d < 256) ? sc[cur][t + d] : 0);
        sc[nxt][t] = v;
        __syncthreads();
        cur ^= 1; nxt ^= 1;
    }
    int Sincl = sc[cur][t];
    int Sexcl = (t + 1 < 256) ? sc[cur][t + 1] : 0;

    if (t == 0 && Sincl < PREK) { sChunk = 0; sAbove = 0; }
    if (Sincl >= PREK && Sexcl < PREK) { sChunk = t; sAbove = Sexcl; }
    __syncthreads();

    int chunk = sChunk, above = sAbove;
    int h = g_hist[b * NBUCK + chunk * 256 + t];
    sc[cur][t] = h;
    __syncthreads();
#pragma unroll
    for (int d = 1; d < 256; d <<= 1) {
        int v = sc[cur][t] + ((t + d < 256) ? sc[cur][t + d] : 0);
        sc[nxt][t] = v;
        __syncthreads();
        cur ^= 1; nxt ^= 1;
    }
    int inclK = above + sc[cur][t];
    int exclK = above + ((t + 1 < 256) ? sc[cur][t + 1] : 0);
    if (inclK >= PREK && exclK < PREK) g_cut[b] = chunk * 256 + t;
    if (t == 0 && above + sc[cur][0] < PREK) g_cut[b] = chunk * 256;
}

// ---------------- K3: compact candidates >= cutoff bucket (x4 vec) --------
__global__ void k_compact(const int* __restrict__ bidx, int n) {
    int q = blockIdx.x * blockDim.x + threadIdx.x;
    int i0 = q * 4;
    if (i0 >= n) return;
    if (i0 + 3 < n) {
        int4 bv = *reinterpret_cast<const int4*>(bidx + i0);
        uint4 sv = *reinterpret_cast<const uint4*>(g_sbits + i0);
        int bb[4] = {bv.x, bv.y, bv.z, bv.w};
        unsigned ss[4] = {sv.x, sv.y, sv.z, sv.w};
#pragma unroll
        for (int k = 0; k < 4; k++) {
            if ((int)(ss[k] >> 16) >= g_cut[bb[k]]) {
                int pos = atomicAdd(&g_cnt[bb[k]], 1);
                if (pos < CAP)
                    g_cand[bb[k] * CAP + pos] =
                        ((unsigned long long)ss[k] << 32) |
                        (unsigned long long)(0xFFFFFFFFu - (unsigned)(i0 + k));
            }
        }
    } else {
        for (int i = i0; i < n; i++) {
            int b = bidx[i];
            unsigned sb = g_sbits[i];
            if ((int)(sb >> 16) >= g_cut[b]) {
                int pos = atomicAdd(&g_cnt[b], 1);
                if (pos < CAP)
                    g_cand[b * CAP + pos] =
                        ((unsigned long long)sb << 32) |
                        (unsigned long long)(0xFFFFFFFFu - (unsigned)i);
            }
        }
    }
}

// ---------------- K4: per-batch bitonic sort + gather top-1024 ------------
__global__ __launch_bounds__(1024) void k_sort(int n) {
    __shared__ unsigned long long sk[CAP];
    int b = blockIdx.x, t = threadIdx.x;
    int cnt = g_cnt[b]; if (cnt > CAP) cnt = CAP;
#pragma unroll
    for (int r = 0; r < CAP / 1024; r++) {
        int i = t + r * 1024;
        sk[i] = (i < cnt) ? g_cand[b * CAP + i] : 0ULL;
    }
    __syncthreads();
    for (int k = 2; k <= CAP; k <<= 1) {
        for (int j = k >> 1; j > 0; j >>= 1) {
#pragma unroll
            for (int r = 0; r < CAP / 1024; r++) {
                int i = t + r * 1024;
                int l = i ^ j;
                if (l > i) {
                    unsigned long long A = sk[i], B = sk[l];
                    bool desc = ((i & k) == 0);
                    if (desc ? (A < B) : (A > B)) { sk[i] = B; sk[l] = A; }
                }
            }
            __syncthreads();
        }
    }
    if (t < PREK) {
        unsigned long long key = sk[t];
        unsigned idx = 0xFFFFFFFFu - (unsigned)(key & 0xFFFFFFFFull);
        float val = __uint_as_float((unsigned)(key >> 32));
        bool ok = (key != 0ULL) && (idx < (unsigned)n);
        float bx[7];
        if (ok) {
            const float4* p4 = reinterpret_cast<const float4*>(g_boxes + (size_t)idx * 8);
            float4 A = p4[0], B = p4[1];
            bx[0] = A.x; bx[1] = A.y; bx[2] = A.z; bx[3] = A.w;
            bx[4] = B.x; bx[5] = B.y; bx[6] = B.z;
        } else {
#pragma unroll
            for (int c = 0; c < 7; c++) bx[c] = 0.f;
            val = NEGBIG;
        }
        int o = b * PREK + t;
        g_vals[o] = val;
#pragma unroll
        for (int c = 0; c < 7; c++) g_box7[o * 7 + c] = bx[c];
        float hx = bx[3] * 0.5f, hy = bx[4] * 0.5f;
        g_x1[o] = bx[0] - hx; g_x2[o] = bx[0] + hx;
        g_y1[o] = bx[1] - hy; g_y2[o] = bx[1] + hy;
        g_ar[o] = bx[3] * bx[4];
    }
}

// ---------------- K5: iou — warp per (row, 32-col chunk), ballot ----------
__global__ __launch_bounds__(256) void k_iou() {
    int wtid = (blockIdx.x * blockDim.x + threadIdx.x) >> 5;
    int lane = threadIdx.x & 31;
    if (wtid >= NBATCH * PREK * 32) return;
    int b = wtid >> 15;
    int i = (wtid >> 5) & (PREK - 1);
    int c = wtid & 31;
    int o = b * PREK;
    int j = c * 32 + lane;

    unsigned w = 0;
    if (c * 32 + 31 > i) {
        float x1 = g_x1[o + i], x2 = g_x2[o + i];
        float y1 = g_y1[o + i], y2 = g_y2[o + i], ar = g_ar[o + i];
        bool hit = false;
        if (j > i) {
            float ix = fmaxf(fminf(x2, g_x2[o + j]) - fmaxf(x1, g_x1[o + j]), 0.f);
            float iy = fmaxf(fminf(y2, g_y2[o + j]) - fmaxf(y1, g_y1[o + j]), 0.f);
            float inter = ix * iy;
            float uni = ar + g_ar[o + j] - inter;
            hit = (inter / fmaxf(uni, 1e-6f)) > 0.1f;
        }
        w = __ballot_sync(0xffffffffu, hit);
    }
    if (lane == 0) {
        g_rows[((size_t)(o + i)) * 32 + c] = w;
        if (w) atomicOr(&g_rowAny[b * 32 + (i >> 5)], 1u << (i & 31));
    }
}

// ---------------- K6: sparse sequential NMS scan + output -----------------
__global__ __launch_bounds__(1024) void k_nms_out(float* __restrict__ out, int out_size) {
    __shared__ unsigned supp[32];
    int b = blockIdx.x, t = threadIdx.x;
    if (t < 32) {
        unsigned sup = 0;
        unsigned myAny = g_rowAny[b * 32 + t];
        for (int w = 0; w < 32; w++) {
            unsigned aw = __shfl_sync(0xffffffffu, myAny, w);
            while (aw) {
                int bit = __ffs(aw) - 1;
                aw &= aw - 1;
                int i = w * 32 + bit;
                unsigned sw = __shfl_sync(0xffffffffu, sup, i >> 5);
                if (!((sw >> (i & 31)) & 1u))
                    sup |= g_rows[((size_t)(b * PREK + i)) * 32 + t];
            }
        }
        supp[t] = sup;
    }
    __syncthreads();
    int o = b * PREK + t;
    float val = g_vals[o];
    bool valid = val > -5e8f;
    bool kp = valid && !((supp[t >> 5] >> (t & 31)) & 1u);
    float m = kp ? 1.f : 0.f;
    size_t base = (size_t)o * 8;
#pragma unroll
    for (int c = 0; c < 7; c++)
        if ((int)(base + c) < out_size) out[base + c] = g_box7[o * 7 + c] * m;
    if ((int)(base + 7) < out_size) out[base + 7] = val * m;
    size_t lbOff = (size_t)NBATCH * PREK * 8 + o;
    if ((int)lbOff < out_size) out[lbOff] = 0.f;
    size_t kpOff = (size_t)NBATCH * PREK * 9 + o;
    if ((int)kpOff < out_size) out[kpOff] = m;
}

// ---------------- launch ----------------
extern "C" void kernel_launch(void* const* d_in, const int* in_sizes, int n_in,
                              void* d_out, int out_size) {
    const float* feat = (const float*)d_in[0];
    const int*   bidx = (const int*)  d_in[1];
    const int*   coor = (const int*)  d_in[2];
    const float* Wc   = (const float*)d_in[3];
    const float* bc   = (const float*)d_in[4];
    const float* Wr   = (const float*)d_in[5];
    const float* br   = (const float*)d_in[6];
    int n = in_sizes[1];

    k_gemv   <<<GEMV_BLOCKS, 256>>>(feat, Wc, Wr, n);   // also zeroes scratch
    k_decode <<<(n + 255) / 256, 256>>>(bidx, coor, bc, br, n);
    k_cutoff <<<NBATCH, 256>>>();
    k_compact<<<((n + 3) / 4 + 255) / 256, 256>>>(bidx, n);
    k_sort   <<<NBATCH, 1024>>>(n);
    k_iou    <<<(NBATCH * PREK * 32 * 32 + 255) / 256, 256>>>();
    k_nms_out<<<NBATCH, 1024>>>((float*)d_out, out_size);
}